// round 8
// baseline (speedup 1.0000x reference)
#include <cuda_runtime.h>
#include <cuda_fp8.h>
#include <cuda_fp16.h>

#define NN 4096
#define DD 128
#define EPSV 1e-8f
#define N_ITER 100

// -(1/REG) * log2(e), REG = 0.05
#define NEG_INVREG_LOG2E (-28.853900817779268f)
#define REG_F 0.05f
#define MU (1.0f / 4096.0f)
#define NU (1.0f / 4096.0f)

#define MAT_ELEMS 16777216ull   // 4096*4096

// ---------------- device scratch (allocation-free rule: __device__ globals) ----
__device__ unsigned char g_K8[3ull * MAT_ELEMS];  // 48 MB: fp8 e4m3 K, all 3 pairs
__device__ float g_u[3][NN];
__device__ float g_vp[4][3][NN];   // colpass partial sums (4 row quarters)
__device__ float g_sq[3][NN];
__device__ float g_part[384];

// decode 4 packed fp8 e4m3 -> float4 (hardware cvt, subnormal-correct)
__device__ __forceinline__ float4 dec4(unsigned int w32) {
    __half2_raw hlo = __nv_cvt_fp8x2_to_halfraw2((__nv_fp8x2_storage_t)(w32 & 0xFFFFu), __NV_E4M3);
    __half2_raw hhi = __nv_cvt_fp8x2_to_halfraw2((__nv_fp8x2_storage_t)(w32 >> 16), __NV_E4M3);
    float2 lo = __half22float2(*(__half2*)&hlo);
    float2 hi = __half22float2(*(__half2*)&hhi);
    return make_float4(lo.x, lo.y, hi.x, hi.y);
}

// ---------------- kernels ----------------------------------------------------

// all three inputs' squared row norms in one launch. grid 1536 x 256.
__global__ void __launch_bounds__(256) rownorm_all_kernel(
        const float* __restrict__ z0, const float* __restrict__ z1,
        const float* __restrict__ z2) {
    int which = blockIdx.x >> 9;
    int bb    = blockIdx.x & 511;
    const float* x = (which == 0) ? z0 : ((which == 1) ? z1 : z2);
    int row  = bb * 8 + (threadIdx.x >> 5);
    int lane = threadIdx.x & 31;
    const float4* xr = (const float4*)(x + (size_t)row * DD);
    float4 a = xr[lane];
    float s = a.x * a.x + a.y * a.y + a.z * a.z + a.w * a.w;
    #pragma unroll
    for (int o = 16; o; o >>= 1) s += __shfl_xor_sync(0xffffffffu, s, o);
    if (lane == 0) g_sq[which][row] = s;
}

// Build K (fp8) for pair p: 64x64 tile per block, 256 threads, 4x4 per thread.
// R3 structure (scalar smem inner loop, [65] pad) — measured 165us vs 264us
// for the float4-smem variant (which had 8-way bank conflicts).
__global__ void __launch_bounds__(256) build_kernel(
        const float* __restrict__ X, const float* __restrict__ Y,
        int ia, int ib, int p) {
    __shared__ float xs[64][65];
    __shared__ float ys[64][65];

    int tx = threadIdx.x & 15;
    int ty = threadIdx.x >> 4;
    int r0 = blockIdx.y * 64;
    int c0 = blockIdx.x * 64;

    float acc[4][4];
    #pragma unroll
    for (int i = 0; i < 4; i++)
        #pragma unroll
        for (int j = 0; j < 4; j++) acc[i][j] = 0.0f;

    for (int k0 = 0; k0 < DD; k0 += 64) {
        int kq = (threadIdx.x & 15) * 4;
        int rb = threadIdx.x >> 4;
        #pragma unroll
        for (int it = 0; it < 4; it++) {
            int r = rb + it * 16;
            float4 vx = *(const float4*)(X + (size_t)(r0 + r) * DD + k0 + kq);
            xs[r][kq] = vx.x; xs[r][kq + 1] = vx.y; xs[r][kq + 2] = vx.z; xs[r][kq + 3] = vx.w;
            float4 vy = *(const float4*)(Y + (size_t)(c0 + r) * DD + k0 + kq);
            ys[r][kq] = vy.x; ys[r][kq + 1] = vy.y; ys[r][kq + 2] = vy.z; ys[r][kq + 3] = vy.w;
        }
        __syncthreads();

        #pragma unroll 16
        for (int kk = 0; kk < 64; kk++) {
            float xv[4], yv[4];
            #pragma unroll
            for (int i = 0; i < 4; i++) xv[i] = xs[ty * 4 + i][kk];
            #pragma unroll
            for (int j = 0; j < 4; j++) yv[j] = ys[tx * 4 + j][kk];
            #pragma unroll
            for (int i = 0; i < 4; i++)
                #pragma unroll
                for (int j = 0; j < 4; j++) acc[i][j] += xv[i] * yv[j];
        }
        __syncthreads();
    }

    unsigned char* Kp = g_K8 + (size_t)p * MAT_ELEMS;
    #pragma unroll
    for (int i = 0; i < 4; i++) {
        int r = r0 + ty * 4 + i;
        float xq = g_sq[ia][r];
        unsigned int pk = 0;
        #pragma unroll
        for (int j = 0; j < 4; j++) {
            int c = c0 + tx * 4 + j;
            float Cij = fmaxf(xq + g_sq[ib][c] - 2.0f * acc[i][j], 0.0f);
            float kf = exp2f(Cij * NEG_INVREG_LOG2E);
            pk |= (unsigned int)__nv_cvt_float_to_fp8(kf, __NV_SATFINITE, __NV_E4M3) << (8 * j);
        }
        *(unsigned int*)(Kp + (size_t)r * NN + c0 + tx * 4) = pk;
    }
}

__global__ void __launch_bounds__(256) init_u_kernel() {
    int i = blockIdx.x * blockDim.x + threadIdx.x;
    if (i < 3 * NN) ((float*)g_u)[i] = 1.0f;
}

// colpass: partial of sum_i K[i][j]*u[i] over one row quarter (1024 rows).
// grid 384 = 3 pairs x (32 colgroups x 4 quarters); block 256 (8 warps).
// Lane loads uint = 4 fp8 cols -> warp covers 128 contiguous cols.
__global__ void __launch_bounds__(256) colpass_kernel() {
    __shared__ float us[1024];        // 4 KB
    __shared__ float red[8][128];     // 4 KB

    int b   = blockIdx.x;
    int p   = b >> 7;                 // /128
    int rem = b & 127;
    int q   = rem >> 5;               // row quarter 0..3
    int j0  = (rem & 31) << 7;        // col group * 128
    int r0  = q << 10;                // * 1024

    for (int i = threadIdx.x; i < 1024; i += 256) us[i] = g_u[p][r0 + i];
    __syncthreads();

    int w = threadIdx.x >> 5, lane = threadIdx.x & 31;
    const unsigned int* Kc =
        (const unsigned int*)(g_K8 + (size_t)p * MAT_ELEMS + (size_t)r0 * NN + j0);
    float a0 = 0.f, a1 = 0.f, a2 = 0.f, a3 = 0.f;
    #pragma unroll 8
    for (int i = w; i < 1024; i += 8) {
        unsigned int kw = Kc[(size_t)i * 1024 + lane];
        float ur = us[i];
        float4 k = dec4(kw);
        a0 += k.x * ur; a1 += k.y * ur; a2 += k.z * ur; a3 += k.w * ur;
    }
    *(float4*)&red[w][lane * 4] = make_float4(a0, a1, a2, a3);
    __syncthreads();
    if (threadIdx.x < 128) {
        float s = 0.f;
        #pragma unroll
        for (int ww = 0; ww < 8; ww++) s += red[ww][threadIdx.x];
        g_vp[q][p][j0 + threadIdx.x] = s;       // raw partial
    }
}

// rowpass: u[i] = MU / (sum_j K[i][j] * v[j] + eps).
// v combined from 4 colpass partials during smem staging.
// grid 384 (3 x 128 rowgroups of 32); block 256, warp handles 4 rows.
__global__ void __launch_bounds__(256) rowpass_kernel() {
    __shared__ float vs[NN];          // 16 KB

    int p  = blockIdx.x >> 7;
    int r0 = (blockIdx.x & 127) << 5;

    const float* q0 = g_vp[0][p];
    const float* q1 = g_vp[1][p];
    const float* q2 = g_vp[2][p];
    const float* q3 = g_vp[3][p];
    for (int i = threadIdx.x; i < NN; i += 256)
        vs[i] = NU / (q0[i] + q1[i] + q2[i] + q3[i] + EPSV);
    __syncthreads();

    const float4* vs4 = (const float4*)vs;
    int w = threadIdx.x >> 5, lane = threadIdx.x & 31;
    #pragma unroll
    for (int rr = 0; rr < 4; rr++) {
        int r = r0 + w + rr * 8;
        const uint4* Kr = (const uint4*)(g_K8 + (size_t)p * MAT_ELEMS + (size_t)r * NN);
        float acc = 0.f;
        #pragma unroll 4
        for (int it = 0; it < 8; it++) {
            uint4 kq = Kr[it * 32 + lane];
            int jb4 = (it * 512 + lane * 16) >> 2;
            float4 k0 = dec4(kq.x), k1 = dec4(kq.y), k2 = dec4(kq.z), k3 = dec4(kq.w);
            float4 v0 = vs4[jb4], v1 = vs4[jb4 + 1], v2 = vs4[jb4 + 2], v3 = vs4[jb4 + 3];
            acc += k0.x * v0.x + k0.y * v0.y + k0.z * v0.z + k0.w * v0.w
                 + k1.x * v1.x + k1.y * v1.y + k1.z * v1.z + k1.w * v1.w
                 + k2.x * v2.x + k2.y * v2.y + k2.z * v2.z + k2.w * v2.w
                 + k3.x * v3.x + k3.y * v3.y + k3.z * v3.z + k3.w * v3.w;
        }
        #pragma unroll
        for (int o = 16; o; o >>= 1) acc += __shfl_xor_sync(0xffffffffu, acc, o);
        if (lane == 0) g_u[p][r] = MU / (acc + EPSV);
    }
}

// loss partials: sum u_i * (K*C)(byte) * v_j, (K*C) via 256-entry smem LUT.
// grid 384 (3 x 128 rowgroups of 32); block 256, warp handles 4 rows.
__global__ void __launch_bounds__(256) loss_kernel() {
    __shared__ float vs[NN];
    __shared__ float lutKC[256];
    __shared__ float red[8];

    int p  = blockIdx.x >> 7;
    int r0 = (blockIdx.x & 127) << 5;

    {
        __half2_raw h = __nv_cvt_fp8x2_to_halfraw2((__nv_fp8x2_storage_t)threadIdx.x, __NV_E4M3);
        float k = __half2float(((__half2*)&h)->x);
        // C = -REG * ln(K); entry = K * C. k==0 or NaN -> 0.
        lutKC[threadIdx.x] = (k > 0.f) ? (-REG_F) * logf(k) * k : 0.f;
    }
    const float* q0 = g_vp[0][p];
    const float* q1 = g_vp[1][p];
    const float* q2 = g_vp[2][p];
    const float* q3 = g_vp[3][p];
    for (int i = threadIdx.x; i < NN; i += 256)
        vs[i] = NU / (q0[i] + q1[i] + q2[i] + q3[i] + EPSV);
    __syncthreads();

    int w = threadIdx.x >> 5, lane = threadIdx.x & 31;
    float wtot = 0.f;
    for (int rr = 0; rr < 4; rr++) {
        int r = r0 + w + rr * 8;
        const uint4* Kr = (const uint4*)(g_K8 + (size_t)p * MAT_ELEMS + (size_t)r * NN);
        float acc = 0.f;
        for (int it = 0; it < 8; it++) {
            uint4 kq = Kr[it * 32 + lane];
            int jb = it * 512 + lane * 16;
            unsigned int ww;
            ww = kq.x;
            acc += lutKC[ww & 255] * vs[jb +  0] + lutKC[(ww >>  8) & 255] * vs[jb +  1]
                 + lutKC[(ww >> 16) & 255] * vs[jb +  2] + lutKC[ww >> 24] * vs[jb +  3];
            ww = kq.y;
            acc += lutKC[ww & 255] * vs[jb +  4] + lutKC[(ww >>  8) & 255] * vs[jb +  5]
                 + lutKC[(ww >> 16) & 255] * vs[jb +  6] + lutKC[ww >> 24] * vs[jb +  7];
            ww = kq.z;
            acc += lutKC[ww & 255] * vs[jb +  8] + lutKC[(ww >>  8) & 255] * vs[jb +  9]
                 + lutKC[(ww >> 16) & 255] * vs[jb + 10] + lutKC[ww >> 24] * vs[jb + 11];
            ww = kq.w;
            acc += lutKC[ww & 255] * vs[jb + 12] + lutKC[(ww >>  8) & 255] * vs[jb + 13]
                 + lutKC[(ww >> 16) & 255] * vs[jb + 14] + lutKC[ww >> 24] * vs[jb + 15];
        }
        #pragma unroll
        for (int o = 16; o; o >>= 1) acc += __shfl_xor_sync(0xffffffffu, acc, o);
        if (lane == 0) wtot += acc * g_u[p][r];
    }
    if (lane == 0) red[w] = wtot;
    __syncthreads();
    if (threadIdx.x == 0) {
        float s = 0.f;
        #pragma unroll
        for (int ww = 0; ww < 8; ww++) s += red[ww];
        g_part[blockIdx.x] = s;
    }
}

// deterministic final reduce of 384 partials
__global__ void __launch_bounds__(128) reduce_part_kernel(float* out) {
    __shared__ float red[128];
    float s = 0.f;
    for (int i = threadIdx.x; i < 384; i += 128) s += g_part[i];
    red[threadIdx.x] = s;
    __syncthreads();
    for (int st = 64; st; st >>= 1) {
        if (threadIdx.x < st) red[threadIdx.x] += red[threadIdx.x + st];
        __syncthreads();
    }
    if (threadIdx.x == 0) out[0] = red[0] * (1.0f / 3.0f);
}

// ---------------- launch ------------------------------------------------------

extern "C" void kernel_launch(void* const* d_in, const int* in_sizes, int n_in,
                              void* d_out, int out_size) {
    (void)in_sizes; (void)n_in; (void)out_size;
    const float* z[3] = { (const float*)d_in[0], (const float*)d_in[1], (const float*)d_in[2] };

    rownorm_all_kernel<<<1536, 256>>>(z[0], z[1], z[2]);

    const int pairs[3][2] = { {0, 1}, {0, 2}, {1, 2} };
    dim3 bgrid(64, 64);
    for (int pp = 0; pp < 3; pp++)
        build_kernel<<<bgrid, 256>>>(z[pairs[pp][0]], z[pairs[pp][1]],
                                     pairs[pp][0], pairs[pp][1], pp);

    init_u_kernel<<<48, 256>>>();

    for (int it = 0; it < N_ITER; it++) {
        colpass_kernel<<<384, 256>>>();
        rowpass_kernel<<<384, 256>>>();
    }

    loss_kernel<<<384, 256>>>();
    reduce_part_kernel<<<1, 128>>>((float*)d_out);
}

// round 9
// speedup vs baseline: 1.0001x; 1.0001x over previous
#include <cuda_runtime.h>
#include <cuda_fp8.h>
#include <cuda_fp16.h>

#define NN 4096
#define DD 128
#define EPSV 1e-8f
#define N_ITER 100

// -(1/REG) * log2(e), REG = 0.05
#define NEG_INVREG_LOG2E (-28.853900817779268f)
#define REG_F 0.05f
#define MU (1.0f / 4096.0f)
#define NU (1.0f / 4096.0f)

#define MAT_ELEMS 16777216ull   // 4096*4096
#define PGRID 384               // persistent grid size

// ---------------- device scratch (allocation-free rule: __device__ globals) ----
__device__ unsigned char g_K8[3ull * MAT_ELEMS];  // 48 MB: fp8 e4m3 K, all 3 pairs
__device__ float g_u[3][NN];
__device__ float g_vp[4][3][NN];   // colpass partial sums (4 row quarters)
__device__ float g_sq[3][NN];
__device__ float g_part[384];
__device__ unsigned int g_barc;    // grid barrier: arrival counter
__device__ unsigned int g_barg;    // grid barrier: generation

// decode 4 packed fp8 e4m3 -> float4 (hardware cvt, subnormal-correct)
__device__ __forceinline__ float4 dec4(unsigned int w32) {
    __half2_raw hlo = __nv_cvt_fp8x2_to_halfraw2((__nv_fp8x2_storage_t)(w32 & 0xFFFFu), __NV_E4M3);
    __half2_raw hhi = __nv_cvt_fp8x2_to_halfraw2((__nv_fp8x2_storage_t)(w32 >> 16), __NV_E4M3);
    float2 lo = __half22float2(*(__half2*)&hlo);
    float2 hi = __half22float2(*(__half2*)&hhi);
    return make_float4(lo.x, lo.y, hi.x, hi.y);
}

// grid-wide barrier (all PGRID blocks co-resident — see launch_bounds proof)
__device__ __forceinline__ void grid_sync() {
    __syncthreads();
    if (threadIdx.x == 0) {
        volatile unsigned int* genp = &g_barg;
        unsigned int gen = *genp;                 // read BEFORE arrival
        __threadfence();                          // publish my writes
        unsigned int t = atomicAdd(&g_barc, 1);
        if (t == PGRID - 1) {
            g_barc = 0;
            __threadfence();
            atomicExch(&g_barg, gen + 1);         // release
        } else {
            while (*genp == gen) __nanosleep(64);
        }
    }
    __syncthreads();
}

// ---------------- kernels ----------------------------------------------------

// all three inputs' squared row norms in one launch. grid 1536 x 256.
__global__ void __launch_bounds__(256) rownorm_all_kernel(
        const float* __restrict__ z0, const float* __restrict__ z1,
        const float* __restrict__ z2) {
    int which = blockIdx.x >> 9;
    int bb    = blockIdx.x & 511;
    const float* x = (which == 0) ? z0 : ((which == 1) ? z1 : z2);
    int row  = bb * 8 + (threadIdx.x >> 5);
    int lane = threadIdx.x & 31;
    const float4* xr = (const float4*)(x + (size_t)row * DD);
    float4 a = xr[lane];
    float s = a.x * a.x + a.y * a.y + a.z * a.z + a.w * a.w;
    #pragma unroll
    for (int o = 16; o; o >>= 1) s += __shfl_xor_sync(0xffffffffu, s, o);
    if (lane == 0) g_sq[which][row] = s;
}

// Build K (fp8) for pair p: 64x64 tile per block, 256 threads, 4x4 per thread.
// R3 structure (scalar smem inner loop, [65] pad) — measured 165us vs 264us
// for the float4-smem variant (8-way bank conflicts).
__global__ void __launch_bounds__(256) build_kernel(
        const float* __restrict__ X, const float* __restrict__ Y,
        int ia, int ib, int p) {
    __shared__ float xs[64][65];
    __shared__ float ys[64][65];

    int tx = threadIdx.x & 15;
    int ty = threadIdx.x >> 4;
    int r0 = blockIdx.y * 64;
    int c0 = blockIdx.x * 64;

    float acc[4][4];
    #pragma unroll
    for (int i = 0; i < 4; i++)
        #pragma unroll
        for (int j = 0; j < 4; j++) acc[i][j] = 0.0f;

    for (int k0 = 0; k0 < DD; k0 += 64) {
        int kq = (threadIdx.x & 15) * 4;
        int rb = threadIdx.x >> 4;
        #pragma unroll
        for (int it = 0; it < 4; it++) {
            int r = rb + it * 16;
            float4 vx = *(const float4*)(X + (size_t)(r0 + r) * DD + k0 + kq);
            xs[r][kq] = vx.x; xs[r][kq + 1] = vx.y; xs[r][kq + 2] = vx.z; xs[r][kq + 3] = vx.w;
            float4 vy = *(const float4*)(Y + (size_t)(c0 + r) * DD + k0 + kq);
            ys[r][kq] = vy.x; ys[r][kq + 1] = vy.y; ys[r][kq + 2] = vy.z; ys[r][kq + 3] = vy.w;
        }
        __syncthreads();

        #pragma unroll 16
        for (int kk = 0; kk < 64; kk++) {
            float xv[4], yv[4];
            #pragma unroll
            for (int i = 0; i < 4; i++) xv[i] = xs[ty * 4 + i][kk];
            #pragma unroll
            for (int j = 0; j < 4; j++) yv[j] = ys[tx * 4 + j][kk];
            #pragma unroll
            for (int i = 0; i < 4; i++)
                #pragma unroll
                for (int j = 0; j < 4; j++) acc[i][j] += xv[i] * yv[j];
        }
        __syncthreads();
    }

    unsigned char* Kp = g_K8 + (size_t)p * MAT_ELEMS;
    #pragma unroll
    for (int i = 0; i < 4; i++) {
        int r = r0 + ty * 4 + i;
        float xq = g_sq[ia][r];
        unsigned int pk = 0;
        #pragma unroll
        for (int j = 0; j < 4; j++) {
            int c = c0 + tx * 4 + j;
            float Cij = fmaxf(xq + g_sq[ib][c] - 2.0f * acc[i][j], 0.0f);
            float kf = exp2f(Cij * NEG_INVREG_LOG2E);
            pk |= (unsigned int)__nv_cvt_float_to_fp8(kf, __NV_SATFINITE, __NV_E4M3) << (8 * j);
        }
        *(unsigned int*)(Kp + (size_t)r * NN + c0 + tx * 4) = pk;
    }
}

// init u = 1 and reset the grid barrier (runs every replay -> deterministic)
__global__ void __launch_bounds__(256) init_u_kernel() {
    int i = blockIdx.x * blockDim.x + threadIdx.x;
    if (i < 3 * NN) ((float*)g_u)[i] = 1.0f;
    if (i == 0) { g_barc = 0u; g_barg = 0u; }
}

// Persistent Sinkhorn: all 100 iterations in one launch, grid barrier between
// phases. 384 blocks x 256 threads; all blocks co-resident (see launch_bounds).
// Block b: colpass tile = (pair p, row-quarter q, 128-col group j0)
//          rowpass tile = (pair p, 32-row group r0r)
// Cross-block data (u, vp) via __ldcg/__stcg (L2-only; L1 is not coherent
// across SMs within a launch). K via plain LDG (read-only).
__global__ void __launch_bounds__(256, 4) sinkhorn_kernel() {
    __shared__ float vs[NN];          // 16 KB (rowpass v; colpass reuses first 1 KB... no: colpass uses own region)
    __shared__ float red[8][128];     // 4 KB

    int b   = blockIdx.x;
    int p   = b >> 7;                 // pair 0..2
    int rem = b & 127;
    int q   = rem >> 5;               // row quarter 0..3
    int j0  = (rem & 31) << 7;        // col group * 128
    int r0c = q << 10;                // colpass row base
    int r0r = rem << 5;               // rowpass row base (32 rows)

    int w = threadIdx.x >> 5, lane = threadIdx.x & 31;

    const unsigned int* Kc =
        (const unsigned int*)(g_K8 + (size_t)p * MAT_ELEMS + (size_t)r0c * NN + j0);
    const float* q0 = g_vp[0][p];
    const float* q1 = g_vp[1][p];
    const float* q2 = g_vp[2][p];
    const float* q3 = g_vp[3][p];

    for (int it = 0; it < N_ITER; it++) {
        // ---- colpass: partial over 1024 rows for 128 cols ----
        for (int i = threadIdx.x; i < 1024; i += 256)
            vs[i] = __ldcg(&g_u[p][r0c + i]);
        __syncthreads();

        float a0 = 0.f, a1 = 0.f, a2 = 0.f, a3 = 0.f;
        #pragma unroll 8
        for (int i = w; i < 1024; i += 8) {
            unsigned int kw = Kc[(size_t)i * 1024 + lane];
            float ur = vs[i];
            float4 k = dec4(kw);
            a0 += k.x * ur; a1 += k.y * ur; a2 += k.z * ur; a3 += k.w * ur;
        }
        *(float4*)&red[w][lane * 4] = make_float4(a0, a1, a2, a3);
        __syncthreads();
        if (threadIdx.x < 128) {
            float s = 0.f;
            #pragma unroll
            for (int ww = 0; ww < 8; ww++) s += red[ww][threadIdx.x];
            __stcg(&g_vp[q][p][j0 + threadIdx.x], s);
        }
        grid_sync();

        // ---- rowpass: combine v, then 32 rows of u ----
        for (int i = threadIdx.x; i < NN; i += 256)
            vs[i] = NU / (__ldcg(q0 + i) + __ldcg(q1 + i) +
                          __ldcg(q2 + i) + __ldcg(q3 + i) + EPSV);
        __syncthreads();

        const float4* vs4 = (const float4*)vs;
        #pragma unroll
        for (int rr = 0; rr < 4; rr++) {
            int r = r0r + w + rr * 8;
            const uint4* Kr = (const uint4*)(g_K8 + (size_t)p * MAT_ELEMS + (size_t)r * NN);
            float acc = 0.f;
            #pragma unroll 4
            for (int itk = 0; itk < 8; itk++) {
                uint4 kq = Kr[itk * 32 + lane];
                int jb4 = (itk * 512 + lane * 16) >> 2;
                float4 k0 = dec4(kq.x), k1 = dec4(kq.y), k2 = dec4(kq.z), k3 = dec4(kq.w);
                float4 v0 = vs4[jb4], v1 = vs4[jb4 + 1], v2 = vs4[jb4 + 2], v3 = vs4[jb4 + 3];
                acc += k0.x * v0.x + k0.y * v0.y + k0.z * v0.z + k0.w * v0.w
                     + k1.x * v1.x + k1.y * v1.y + k1.z * v1.z + k1.w * v1.w
                     + k2.x * v2.x + k2.y * v2.y + k2.z * v2.z + k2.w * v2.w
                     + k3.x * v3.x + k3.y * v3.y + k3.z * v3.z + k3.w * v3.w;
            }
            #pragma unroll
            for (int o = 16; o; o >>= 1) acc += __shfl_xor_sync(0xffffffffu, acc, o);
            if (lane == 0) __stcg(&g_u[p][r], MU / (acc + EPSV));
        }
        grid_sync();
        __syncthreads();   // vs reuse safety for next colpass stage
    }
}

// loss partials: sum u_i * (K*C)(byte) * v_j, (K*C) via 256-entry smem LUT.
// grid 384 (3 x 128 rowgroups of 32); block 256, warp handles 4 rows.
__global__ void __launch_bounds__(256) loss_kernel() {
    __shared__ float vs[NN];
    __shared__ float lutKC[256];
    __shared__ float red[8];

    int p  = blockIdx.x >> 7;
    int r0 = (blockIdx.x & 127) << 5;

    {
        __half2_raw h = __nv_cvt_fp8x2_to_halfraw2((__nv_fp8x2_storage_t)threadIdx.x, __NV_E4M3);
        float k = __half2float(((__half2*)&h)->x);
        lutKC[threadIdx.x] = (k > 0.f) ? (-REG_F) * logf(k) * k : 0.f;
    }
    const float* q0 = g_vp[0][p];
    const float* q1 = g_vp[1][p];
    const float* q2 = g_vp[2][p];
    const float* q3 = g_vp[3][p];
    for (int i = threadIdx.x; i < NN; i += 256)
        vs[i] = NU / (q0[i] + q1[i] + q2[i] + q3[i] + EPSV);
    __syncthreads();

    int w = threadIdx.x >> 5, lane = threadIdx.x & 31;
    float wtot = 0.f;
    for (int rr = 0; rr < 4; rr++) {
        int r = r0 + w + rr * 8;
        const uint4* Kr = (const uint4*)(g_K8 + (size_t)p * MAT_ELEMS + (size_t)r * NN);
        float acc = 0.f;
        for (int it = 0; it < 8; it++) {
            uint4 kq = Kr[it * 32 + lane];
            int jb = it * 512 + lane * 16;
            unsigned int ww;
            ww = kq.x;
            acc += lutKC[ww & 255] * vs[jb +  0] + lutKC[(ww >>  8) & 255] * vs[jb +  1]
                 + lutKC[(ww >> 16) & 255] * vs[jb +  2] + lutKC[ww >> 24] * vs[jb +  3];
            ww = kq.y;
            acc += lutKC[ww & 255] * vs[jb +  4] + lutKC[(ww >>  8) & 255] * vs[jb +  5]
                 + lutKC[(ww >> 16) & 255] * vs[jb +  6] + lutKC[ww >> 24] * vs[jb +  7];
            ww = kq.z;
            acc += lutKC[ww & 255] * vs[jb +  8] + lutKC[(ww >>  8) & 255] * vs[jb +  9]
                 + lutKC[(ww >> 16) & 255] * vs[jb + 10] + lutKC[ww >> 24] * vs[jb + 11];
            ww = kq.w;
            acc += lutKC[ww & 255] * vs[jb + 12] + lutKC[(ww >>  8) & 255] * vs[jb + 13]
                 + lutKC[(ww >> 16) & 255] * vs[jb + 14] + lutKC[ww >> 24] * vs[jb + 15];
        }
        #pragma unroll
        for (int o = 16; o; o >>= 1) acc += __shfl_xor_sync(0xffffffffu, acc, o);
        if (lane == 0) wtot += acc * g_u[p][r];
    }
    if (lane == 0) red[w] = wtot;
    __syncthreads();
    if (threadIdx.x == 0) {
        float s = 0.f;
        #pragma unroll
        for (int ww = 0; ww < 8; ww++) s += red[ww];
        g_part[blockIdx.x] = s;
    }
}

// deterministic final reduce of 384 partials
__global__ void __launch_bounds__(128) reduce_part_kernel(float* out) {
    __shared__ float red[128];
    float s = 0.f;
    for (int i = threadIdx.x; i < 384; i += 128) s += g_part[i];
    red[threadIdx.x] = s;
    __syncthreads();
    for (int st = 64; st; st >>= 1) {
        if (threadIdx.x < st) red[threadIdx.x] += red[threadIdx.x + st];
        __syncthreads();
    }
    if (threadIdx.x == 0) out[0] = red[0] * (1.0f / 3.0f);
}

// ---------------- launch ------------------------------------------------------

extern "C" void kernel_launch(void* const* d_in, const int* in_sizes, int n_in,
                              void* d_out, int out_size) {
    (void)in_sizes; (void)n_in; (void)out_size;
    const float* z[3] = { (const float*)d_in[0], (const float*)d_in[1], (const float*)d_in[2] };

    rownorm_all_kernel<<<1536, 256>>>(z[0], z[1], z[2]);

    const int pairs[3][2] = { {0, 1}, {0, 2}, {1, 2} };
    dim3 bgrid(64, 64);
    for (int pp = 0; pp < 3; pp++)
        build_kernel<<<bgrid, 256>>>(z[pairs[pp][0]], z[pairs[pp][1]],
                                     pairs[pp][0], pairs[pp][1], pp);

    init_u_kernel<<<48, 256>>>();

    sinkhorn_kernel<<<PGRID, 256>>>();   // all 100 iterations, one launch

    loss_kernel<<<384, 256>>>();
    reduce_part_kernel<<<1, 128>>>((float*)d_out);
}